// round 1
// baseline (speedup 1.0000x reference)
#include <cuda_runtime.h>
#include <cuda_fp16.h>
#include <cstdint>

#define VOCAB   50000
#define EMB_DIM 300
#define KP      304        // K padded to multiple of 16
#define NTOT    2048
#define MTOT    32768
#define MTILE   256
#define NCHUNK  64
#define ASTR    312        // halves per A row (pad: conflict-free ldmatrix)
#define BSTR    72         // halves per B row (pad: conflict-free ldmatrix)
#define SMEM_BYTES ((MTILE*ASTR + KP*BSTR) * 2)

// fp16 copy of W, zero-padded rows 300..303. Static device scratch (no allocs).
__device__ __half g_Wh[KP * NTOT];

__global__ void prep_w(const float* __restrict__ W) {
    int i = blockIdx.x * blockDim.x + threadIdx.x;
    if (i >= KP * NTOT) return;
    int k = i / NTOT, n = i % NTOT;
    float v = (k < EMB_DIM) ? W[k * NTOT + n] : 0.0f;
    g_Wh[i] = __float2half_rn(v);
}

__device__ __forceinline__ void ldm_x4(uint32_t &r0, uint32_t &r1, uint32_t &r2,
                                       uint32_t &r3, uint32_t a) {
    asm volatile("ldmatrix.sync.aligned.m8n8.x4.shared.b16 {%0,%1,%2,%3}, [%4];"
                 : "=r"(r0), "=r"(r1), "=r"(r2), "=r"(r3) : "r"(a));
}
__device__ __forceinline__ void ldm_x4_t(uint32_t &r0, uint32_t &r1, uint32_t &r2,
                                         uint32_t &r3, uint32_t a) {
    asm volatile("ldmatrix.sync.aligned.m8n8.x4.trans.shared.b16 {%0,%1,%2,%3}, [%4];"
                 : "=r"(r0), "=r"(r1), "=r"(r2), "=r"(r3) : "r"(a));
}
__device__ __forceinline__ void mma16816(float* d, const uint32_t* a, const uint32_t* b) {
    asm volatile("mma.sync.aligned.m16n8k16.row.col.f32.f16.f16.f32 "
                 "{%0,%1,%2,%3}, {%4,%5,%6,%7}, {%8,%9}, {%0,%1,%2,%3};"
                 : "+f"(d[0]), "+f"(d[1]), "+f"(d[2]), "+f"(d[3])
                 : "r"(a[0]), "r"(a[1]), "r"(a[2]), "r"(a[3]),
                   "r"(b[0]), "r"(b[1]));
}

__global__ __launch_bounds__(256, 1)
void gemm_kernel(const int* __restrict__ x, const float* __restrict__ emb,
                 const float* __restrict__ bias, float* __restrict__ out) {
    extern __shared__ __half sm[];
    __half* A_s = sm;                       // [MTILE][ASTR]
    __half* B_s = sm + MTILE * ASTR;        // [KP][BSTR]

    const int tid = threadIdx.x;
    const int m0  = blockIdx.x * MTILE;

    // ---- Gather A: 256 token rows, 8 threads per row, fp32 -> fp16 ----
    {
        int rgrp = tid >> 3;     // 0..31
        int l8   = tid & 7;
        #pragma unroll
        for (int pass = 0; pass < 8; ++pass) {
            int r = pass * 32 + rgrp;
            int token = x[m0 + r];
            const float4* src = (const float4*)(emb + (size_t)token * EMB_DIM); // 16B aligned (1200B rows)
            __half* dstrow = A_s + r * ASTR;
            #pragma unroll
            for (int j = 0; j < 10; ++j) {
                int idx = l8 + 8 * j;            // 75 float4 per row
                if (idx < 75) {
                    float4 v = src[idx];
                    __half2* d2 = (__half2*)(dstrow + 4 * idx);
                    d2[0] = __floats2half2_rn(v.x, v.y);
                    d2[1] = __floats2half2_rn(v.z, v.w);
                }
            }
        }
        // zero K padding cols 300..311
        for (int i = tid; i < MTILE * 12; i += 256) {
            int r = i / 12, c = 300 + (i % 12);
            A_s[r * ASTR + c] = __float2half(0.0f);
        }
    }

    const int lane = tid & 31, wid = tid >> 5;
    const int wm = wid >> 1;        // 0..3 : 64 rows each
    const int wn = wid & 1;         // 0..1 : 32 cols each
    const int bq = lane >> 3, rq = lane & 7;   // ldmatrix address octets

    uint32_t smem_u = (uint32_t)__cvta_generic_to_shared(sm);
    // A lane base: row = wm*64 + (bq&1)*8 + rq, col-bytes = (bq>>1)*16 (+ kb*2 in loop)
    uint32_t aBase = smem_u + (uint32_t)((wm * 64 + (bq & 1) * 8 + rq) * ASTR) * 2
                            + (uint32_t)(bq >> 1) * 16;
    // B lane base: k-row = (bq&1)*8 + rq (+ kb in loop), col-bytes = wn*64 + (bq>>1)*16 (+ p*32)
    uint32_t bBase = smem_u + (uint32_t)(MTILE * ASTR) * 2
                            + (uint32_t)(((bq & 1) * 8 + rq) * BSTR) * 2
                            + (uint32_t)(wn * 64 + (bq >> 1) * 16);

    const float scale = 45.25483399593904f;    // sqrt(2048)

    for (int nc = 0; nc < NTOT / NCHUNK; ++nc) {
        int n0 = nc * NCHUNK;
        __syncthreads();   // protect B_s reuse (and A_s readiness on first iter)

        // ---- load B chunk: B_s[k][n] = W_h[k][n0+n], coalesced 16B copies ----
        for (int i = tid; i < KP * (NCHUNK / 8); i += 256) {
            int k = i >> 3, j = i & 7;
            uint4 v = *(const uint4*)(g_Wh + (size_t)k * NTOT + n0 + 8 * j);
            *(uint4*)(B_s + k * BSTR + 8 * j) = v;
        }
        __syncthreads();

        float acc[4][4][4];
        #pragma unroll
        for (int mt = 0; mt < 4; ++mt)
            #pragma unroll
            for (int nt = 0; nt < 4; ++nt)
                #pragma unroll
                for (int q = 0; q < 4; ++q) acc[mt][nt][q] = 0.0f;

        for (int ks = 0; ks < KP / 16; ++ks) {
            uint32_t a[4][4], b[2][4];
            uint32_t kbA = (uint32_t)ks * 32;              // kb*2 bytes
            uint32_t kbB = (uint32_t)ks * 16 * BSTR * 2;   // k-row advance bytes
            #pragma unroll
            for (int mt = 0; mt < 4; ++mt)
                ldm_x4(a[mt][0], a[mt][1], a[mt][2], a[mt][3],
                       aBase + (uint32_t)(mt * 16 * ASTR) * 2 + kbA);
            #pragma unroll
            for (int p = 0; p < 2; ++p)
                ldm_x4_t(b[p][0], b[p][1], b[p][2], b[p][3],
                         bBase + (uint32_t)p * 32 + kbB);
            #pragma unroll
            for (int mt = 0; mt < 4; ++mt)
                #pragma unroll
                for (int nt = 0; nt < 4; ++nt) {
                    uint32_t bb[2] = { b[nt >> 1][(nt & 1) * 2],
                                       b[nt >> 1][(nt & 1) * 2 + 1] };
                    mma16816(acc[mt][nt], a[mt], bb);
                }
        }

        // ---- epilogue: (acc + bias) * sqrt(d_model), float2 stores ----
        #pragma unroll
        for (int nt = 0; nt < 4; ++nt) {
            int col = n0 + wn * 32 + nt * 8 + (lane & 3) * 2;
            float2 cb = *(const float2*)(bias + col);
            #pragma unroll
            for (int mt = 0; mt < 4; ++mt) {
                int row = m0 + wm * 64 + mt * 16 + (lane >> 2);
                float2 v0 = { (acc[mt][nt][0] + cb.x) * scale,
                              (acc[mt][nt][1] + cb.y) * scale };
                float2 v1 = { (acc[mt][nt][2] + cb.x) * scale,
                              (acc[mt][nt][3] + cb.y) * scale };
                *(float2*)(out + (size_t)row * NTOT + col)       = v0;
                *(float2*)(out + (size_t)(row + 8) * NTOT + col) = v1;
            }
        }
    }
}

extern "C" void kernel_launch(void* const* d_in, const int* in_sizes, int n_in,
                              void* d_out, int out_size) {
    const int*   x    = (const int*)  d_in[0];
    const float* emb  = (const float*)d_in[1];
    const float* W    = (const float*)d_in[2];
    const float* bias = (const float*)d_in[3];
    float*       out  = (float*)      d_out;

    cudaFuncSetAttribute(gemm_kernel, cudaFuncAttributeMaxDynamicSharedMemorySize,
                         SMEM_BYTES);

    prep_w<<<(KP * NTOT + 255) / 256, 256>>>(W);
    gemm_kernel<<<MTOT / MTILE, 256, SMEM_BYTES>>>(x, emb, bias, out);
}